// round 7
// baseline (speedup 1.0000x reference)
#include <cuda_runtime.h>
#include <cstdint>

// Problem dims (fixed by the dataset)
#define N_  64
#define C_  256
#define T_  64
#define V_  50
#define H_  16
#define P_  10
#define TV  (T_ * V_)          // 3200 floats per (n,c) slab

#define NBLOCKS    592          // 148 SMs x 4 co-resident blocks (guaranteed)
#define NWARPS     (NBLOCKS * 8)
#define CHUNK_N    16           // batches per chunk (51.2 MB, L2-resident)
#define NCHUNKS    (N_ / CHUNK_N)        // 4
#define CHUNK_NC   (CHUNK_N * C_)        // 4096 slabs per chunk
#define CHUNK_NP   (CHUNK_N * P_)        // 160 gate groups per chunk

// output column j -> input column v (concat order of PARTS)
__constant__ int c_cmap[V_] = {
    0,1,2,3,20,
    8,9,10,11,23,24,
    16,17,18,19,
    4,5,6,7,21,22,
    12,13,14,15,
    25,26,27,28,45,
    33,34,35,36,48,49,
    41,42,43,44,
    29,30,31,32,46,47,
    37,38,39,40
};
// output column j -> partition
__constant__ int c_pmap[V_] = {
    0,0,0,0,0,
    1,1,1,1,1,1,
    2,2,2,2,
    3,3,3,3,3,3,
    4,4,4,4,
    5,5,5,5,5,
    6,6,6,6,6,6,
    7,7,7,7,
    8,8,8,8,8,8,
    9,9,9,9
};
// partition -> member input columns (padded to 6) and sizes
__constant__ int c_pvs[P_ * 6] = {
    0,1,2,3,20,0,
    8,9,10,11,23,24,
    16,17,18,19,0,0,
    4,5,6,7,21,22,
    12,13,14,15,0,0,
    25,26,27,28,45,0,
    33,34,35,36,48,49,
    41,42,43,44,0,0,
    29,30,31,32,46,47,
    37,38,39,40,0,0
};
__constant__ int c_psize[P_] = {5,6,4,6,4,5,6,4,6,4};

// Scratch (alloc-free rule: __device__ globals). Layout: [n][p][c]
__device__ float g_avg [N_ * P_ * C_];
__device__ float g_max [N_ * P_ * C_];
__device__ float g_gate[N_ * P_ * C_];

// Grid barrier state. Monotonic generation => safe across graph replays.
__device__ unsigned bar_count = 0;
__device__ unsigned bar_gen   = 0;

__device__ __forceinline__ void grid_barrier()
{
    __syncthreads();
    if (threadIdx.x == 0) {
        __threadfence();
        const unsigned g = *(volatile unsigned*)&bar_gen;
        const unsigned old = atomicAdd(&bar_count, 1u);
        if (old == (unsigned)(NBLOCKS - 1)) {
            atomicExch(&bar_count, 0u);
            __threadfence();
            atomicAdd(&bar_gen, 1u);              // release
        } else {
            while (*(volatile unsigned*)&bar_gen == g)
                __nanosleep(64);
        }
    }
    __syncthreads();
}

// ---------------------------------------------------------------------------
// Persistent fused kernel: per chunk (16 batches):
//   phase R: warp-per-slab sum/max reduction   (fills L2 with the chunk)
//   phase G: per-(n,p) MLP gate on blocks 512..591
//   phase S: warp-per-slab gated permuted copy (x reads hit L2)
// ---------------------------------------------------------------------------
__global__ __launch_bounds__(256, 4)
void fused_kernel(const float* __restrict__ x,
                  const float* __restrict__ W1, const float* __restrict__ b1,
                  const float* __restrict__ W2, const float* __restrict__ b2,
                  float* __restrict__ out)
{
    __shared__ float  cs [8][V_ + 2];
    __shared__ float  cmx[8][V_ + 2];
    __shared__ float2 wtab[8][V_];
    __shared__ float  sa[C_];
    __shared__ float  sxm[C_];
    __shared__ float  hs[H_];

    const int tid   = threadIdx.x;
    const int warp  = tid >> 5;
    const int lane  = tid & 31;
    const int gwarp = blockIdx.x * 8 + warp;

    for (int ch = 0; ch < NCHUNKS; ++ch) {
        // ---------------- phase R: reduce ----------------
        if (gwarp < CHUNK_NC) {
            const int nc = ch * CHUNK_NC + gwarp;
            if (lane < 25) {
                const float2* p = (const float2*)x + (size_t)nc * (TV / 2) + lane;
                float sx = 0.f, sy = 0.f;
                float mx = -3.402823466e+38f, my = -3.402823466e+38f;
#pragma unroll 8
                for (int r = 0; r < T_; ++r) {
                    float2 v = p[r * 25];
                    sx += v.x;             sy += v.y;
                    mx = fmaxf(mx, v.x);   my = fmaxf(my, v.y);
                }
                cs [warp][2 * lane]     = sx;
                cs [warp][2 * lane + 1] = sy;
                cmx[warp][2 * lane]     = mx;
                cmx[warp][2 * lane + 1] = my;
            }
            __syncwarp();
            if (lane < P_) {
                const int sz = c_psize[lane];
                float s3 = 0.f, m3 = -3.402823466e+38f;
                for (int j = 0; j < sz; ++j) {
                    const int vv = c_pvs[lane * 6 + j];
                    s3 += cs[warp][vv];
                    m3 = fmaxf(m3, cmx[warp][vv]);
                }
                const int n = nc >> 8;
                const int c = nc & 255;
                const size_t o = ((size_t)n * P_ + lane) * C_ + c;
                g_avg[o] = s3 / (float)(T_ * sz);
                g_max[o] = m3;
            }
        }
        grid_barrier();

        // ---------------- phase G: gate (blocks 512..591, 2 groups each) ----
        if (blockIdx.x >= 512) {
#pragma unroll
            for (int q = 0; q < 2; ++q) {
                const int grp = (blockIdx.x - 512) * 2 + q;   // 0..159
                const int n = ch * CHUNK_N + grp / P_;
                const int p = grp % P_;

                const size_t base = ((size_t)n * P_ + p) * C_;
                sa [tid] = g_avg[base + tid];
                sxm[tid] = g_max[base + tid];
                __syncthreads();

#pragma unroll
                for (int ii = 0; ii < 2; ++ii) {
                    const int i = warp + 8 * ii;
                    const float* w1 = W1 + ((size_t)p * H_ + i) * C_;
                    float da = 0.f, dm = 0.f;
#pragma unroll
                    for (int k = 0; k < 8; ++k) {
                        const int c = lane + 32 * k;
                        const float wv = w1[c];
                        da += wv * sa[c];
                        dm += wv * sxm[c];
                    }
#pragma unroll
                    for (int off = 16; off > 0; off >>= 1) {
                        da += __shfl_down_sync(0xffffffffu, da, off);
                        dm += __shfl_down_sync(0xffffffffu, dm, off);
                    }
                    if (lane == 0) {
                        const float bb = b1[p * H_ + i];
                        hs[i] = fmaxf(da + bb, 0.f) + fmaxf(dm + bb, 0.f);
                    }
                }
                __syncthreads();

                const float* w2 = W2 + ((size_t)p * C_ + tid) * H_;
                float acc = 2.f * b2[p * C_ + tid];
#pragma unroll
                for (int k = 0; k < H_; ++k)
                    acc += w2[k] * hs[k];
                g_gate[base + tid] = 1.f / (1.f + __expf(-acc));
                __syncthreads();
            }
        }
        grid_barrier();

        // ---------------- phase S: scale (x reads hit L2) ----------------
        if (gwarp < CHUNK_NC) {
            const int nc = ch * CHUNK_NC + gwarp;
            const int n = nc >> 8;
            const int c = nc & 255;

            if (lane < 25) {
#pragma unroll
                for (int q = 0; q < 2; ++q) {
                    const int j = lane + 25 * q;
                    float2 t;
                    t.x = g_gate[((size_t)n * P_ + c_pmap[j]) * C_ + c];
                    t.y = __int_as_float(c_cmap[j] - j);
                    wtab[warp][j] = t;
                }
            }
            __syncwarp();

            const float* xb = x   + (size_t)nc * TV;
            float*       ob = out + (size_t)nc * TV;

            int col = lane;                  // (lane + 32m) % 50, incremental
#pragma unroll 4
            for (int m = 0; m < 100; ++m) {
                const int jj = lane + 32 * m;
                const float2 t = wtab[warp][col];
                __stcs(&ob[jj], xb[jj + __float_as_int(t.y)] * t.x);
                col += 32;
                if (col >= V_) col -= V_;
            }
        }
        if (ch < NCHUNKS - 1)
            grid_barrier();     // keep next chunk's reduce off this chunk's L2
    }
}

// ---------------------------------------------------------------------------
extern "C" void kernel_launch(void* const* d_in, const int* in_sizes, int n_in,
                              void* d_out, int out_size)
{
    const float* x  = (const float*)d_in[0];
    const float* W1 = (const float*)d_in[1];
    const float* b1 = (const float*)d_in[2];
    const float* W2 = (const float*)d_in[3];
    const float* b2 = (const float*)d_in[4];

    fused_kernel<<<NBLOCKS, 256>>>(x, W1, b1, W2, b2, (float*)d_out);
}

// round 8
// speedup vs baseline: 1.3913x; 1.3913x over previous
#include <cuda_runtime.h>
#include <cstdint>

// Problem dims (fixed by the dataset)
#define N_  64
#define C_  256
#define T_  64
#define V_  50
#define H_  16
#define P_  10
#define TV  (T_ * V_)          // 3200 floats per (n,c) slab

// output column j -> input column v (concat order of PARTS)
__constant__ int c_cmap[V_] = {
    0,1,2,3,20,
    8,9,10,11,23,24,
    16,17,18,19,
    4,5,6,7,21,22,
    12,13,14,15,
    25,26,27,28,45,
    33,34,35,36,48,49,
    41,42,43,44,
    29,30,31,32,46,47,
    37,38,39,40
};
// output column j -> partition
__constant__ int c_pmap[V_] = {
    0,0,0,0,0,
    1,1,1,1,1,1,
    2,2,2,2,
    3,3,3,3,3,3,
    4,4,4,4,
    5,5,5,5,5,
    6,6,6,6,6,6,
    7,7,7,7,
    8,8,8,8,8,8,
    9,9,9,9
};
// partition -> member input columns (padded to 6) and sizes
__constant__ int c_pvs[P_ * 6] = {
    0,1,2,3,20,0,
    8,9,10,11,23,24,
    16,17,18,19,0,0,
    4,5,6,7,21,22,
    12,13,14,15,0,0,
    25,26,27,28,45,0,
    33,34,35,36,48,49,
    41,42,43,44,0,0,
    29,30,31,32,46,47,
    37,38,39,40,0,0
};
__constant__ int c_psize[P_] = {5,6,4,6,4,5,6,4,6,4};

// Scratch (alloc-free rule: __device__ globals). Layout: [n][p][c]
__device__ float g_avg [N_ * P_ * C_];
__device__ float g_max [N_ * P_ * C_];
__device__ float g_gate[N_ * P_ * C_];

// ---------------------------------------------------------------------------
// Kernel 1: per-(n,c) sum+max over (t, v in part) for all 10 parts.
// One WARP per slab. 2 rows = 100 floats = 25 float4: lane j (<25) owns
// float4 slot j of each of the 32 two-row groups -> 32x LDG.128, columns
// fixed per lane. Even-row-position results go to array A, odd-row to B;
// per-column total = A[c]+B[c]. No __syncthreads.
// ---------------------------------------------------------------------------
__global__ __launch_bounds__(256)
void reduce_kernel(const float4* __restrict__ x4)
{
    __shared__ float sA [8][V_];   // sums, flat position < 50 (even rows)
    __shared__ float sB [8][V_];   // sums, flat position >= 50 (odd rows)
    __shared__ float mA [8][V_];
    __shared__ float mB [8][V_];

    const int warp = threadIdx.x >> 5;
    const int lane = threadIdx.x & 31;
    const int nc   = blockIdx.x * 8 + warp;          // n*C_ + c

    if (lane < 25) {
        const float4* p = x4 + (size_t)nc * (TV / 4) + lane;
        float s0 = 0.f, s1 = 0.f, s2 = 0.f, s3 = 0.f;
        float m0 = -3.402823466e+38f, m1 = m0, m2 = m0, m3 = m0;
#pragma unroll 8
        for (int g = 0; g < 32; ++g) {               // 32 two-row groups
            float4 v = p[g * 25];
            s0 += v.x;  s1 += v.y;  s2 += v.z;  s3 += v.w;
            m0 = fmaxf(m0, v.x);  m1 = fmaxf(m1, v.y);
            m2 = fmaxf(m2, v.z);  m3 = fmaxf(m3, v.w);
        }
        // scatter to even/odd-row arrays; flat positions 4j..4j+3 in [0,100)
        const int base = 4 * lane;
        float ss[4] = {s0, s1, s2, s3};
        float mm[4] = {m0, m1, m2, m3};
#pragma unroll
        for (int e = 0; e < 4; ++e) {
            const int pos = base + e;
            if (pos < V_) { sA[warp][pos] = ss[e];       mA[warp][pos] = mm[e]; }
            else          { sB[warp][pos - V_] = ss[e];  mB[warp][pos - V_] = mm[e]; }
        }
    }
    __syncwarp();

    if (lane < P_) {
        const int sz = c_psize[lane];
        float s3 = 0.f, m3 = -3.402823466e+38f;
        for (int j = 0; j < sz; ++j) {
            const int vv = c_pvs[lane * 6 + j];
            s3 += sA[warp][vv] + sB[warp][vv];
            m3 = fmaxf(m3, fmaxf(mA[warp][vv], mB[warp][vv]));
        }
        const int n = nc >> 8;      // C_ = 256
        const int c = nc & 255;
        const size_t o = ((size_t)n * P_ + lane) * C_ + c;
        g_avg[o] = s3 / (float)(T_ * sz);
        g_max[o] = m3;
    }
}

// ---------------------------------------------------------------------------
// Kernel 2: gate[n,p,c] = sigmoid( W2 @ (relu(W1@avg+b1)+relu(W1@mx+b1)) + 2*b2 )
// One block per (n,p), 256 threads.
// ---------------------------------------------------------------------------
__global__ __launch_bounds__(C_)
void gate_kernel(const float* __restrict__ W1, const float* __restrict__ b1,
                 const float* __restrict__ W2, const float* __restrict__ b2)
{
    const int np = blockIdx.x;
    const int n  = np / P_;
    const int p  = np % P_;
    const int tid = threadIdx.x;

    __shared__ float sa[C_];
    __shared__ float sx[C_];
    __shared__ float hs[H_];

    const size_t base = ((size_t)n * P_ + p) * C_;
    sa[tid] = g_avg[base + tid];
    sx[tid] = g_max[base + tid];
    __syncthreads();

    const int w = tid >> 5;     // warp 0..7
    const int l = tid & 31;

#pragma unroll
    for (int ii = 0; ii < 2; ++ii) {
        const int i = w + 8 * ii;
        const float* w1 = W1 + ((size_t)p * H_ + i) * C_;
        float da = 0.f, dm = 0.f;
#pragma unroll
        for (int k = 0; k < 8; ++k) {
            const int c = l + 32 * k;
            const float wv = w1[c];
            da += wv * sa[c];
            dm += wv * sx[c];
        }
#pragma unroll
        for (int off = 16; off > 0; off >>= 1) {
            da += __shfl_down_sync(0xffffffffu, da, off);
            dm += __shfl_down_sync(0xffffffffu, dm, off);
        }
        if (l == 0) {
            const float bb = b1[p * H_ + i];
            hs[i] = fmaxf(da + bb, 0.f) + fmaxf(dm + bb, 0.f);
        }
    }
    __syncthreads();

    const float* w2 = W2 + ((size_t)p * C_ + tid) * H_;
    float acc = 2.f * b2[p * C_ + tid];
#pragma unroll
    for (int k = 0; k < H_; ++k)
        acc += w2[k] * hs[k];

    g_gate[base + tid] = 1.f / (1.f + __expf(-acc));
}

// ---------------------------------------------------------------------------
// Kernel 3: out[n,c,t,j] = x[n,c,t,cmap[j]] * gate[n, pmap[j], c]
// smem-staged float4 reads, REVERSE block order (consume the x tail that
// reduce left in L2 first). Streaming stores.
// ---------------------------------------------------------------------------
__global__ __launch_bounds__(256)
void scale_kernel(const float4* __restrict__ x4, float* __restrict__ out)
{
    __shared__ float4 sh4[TV / 4];          // 12.8 KB
    __shared__ float2 tab[V_ + 2];          // {gate, int_as_float(cmap[j]-j)}
    float* sh = (float*)sh4;

    const int nc  = (N_ * C_ - 1) - blockIdx.x;      // REVERSE order
    const int tid = threadIdx.x;
    const int n = nc >> 8;
    const int c = nc & 255;

    const float4* xb = x4  + (size_t)nc * (TV / 4);
    float*        ob = out + (size_t)nc * TV;

    // Phase A: coalesced float4 loads into shared; threads <50 stage table
#pragma unroll
    for (int k = 0; k < 3; ++k)
        sh4[tid + 256 * k] = xb[tid + 256 * k];
    if (tid < 32)
        sh4[tid + 768] = xb[tid + 768];
    if (tid < V_) {
        const int j = tid;
        float2 t;
        t.x = g_gate[((size_t)n * P_ + c_pmap[j]) * C_ + c];
        t.y = __int_as_float(c_cmap[j] - j);
        tab[j] = t;
    }
    __syncthreads();

    // Phase B: lane-consecutive elements jj = tid + 256*m (3200 = 12*256+128)
    int col = tid % V_;                 // output column of element tid
#pragma unroll
    for (int m = 0; m < 13; ++m) {
        if (m < 12 || tid < 128) {
            const int jj = tid + 256 * m;
            const float2 t = tab[col];
            __stcs(&ob[jj], sh[jj + __float_as_int(t.y)] * t.x);
        }
        // advance column by 256 mod 50 = 6
        col += 6;
        if (col >= V_) col -= V_;
    }
}

// ---------------------------------------------------------------------------
extern "C" void kernel_launch(void* const* d_in, const int* in_sizes, int n_in,
                              void* d_out, int out_size)
{
    const float* x  = (const float*)d_in[0];
    const float* W1 = (const float*)d_in[1];
    const float* b1 = (const float*)d_in[2];
    const float* W2 = (const float*)d_in[3];
    const float* b2 = (const float*)d_in[4];

    reduce_kernel<<<(N_ * C_) / 8, 256>>>((const float4*)x);
    gate_kernel<<<N_ * P_, C_>>>(W1, b1, W2, b2);
    scale_kernel<<<N_ * C_, 256>>>((const float4*)x, (float*)d_out);
}